// round 12
// baseline (speedup 1.0000x reference)
#include <cuda_runtime.h>
#include <cuda_fp16.h>
#include <cstdint>
#include <math.h>

#define CHN 256
#define TDIM 4096
#define BATCH 16
#define SKIPOFF ((size_t)BATCH*CHN*TDIM)

// single fp16 planes (device globals: allocation-free)
__device__ __half g_x[(size_t)BATCH*4104*CHN];
__device__ __half g_z[(size_t)BATCH*TDIM*CHN];
__device__ __half g_w1[4*128*512];
__device__ __half g_w2[4*128*256];

// stage: A 64 rows x 80B | B 128 rows x 80B
#define ASTG 5120
#define STG  15360
#define NSTG 4
#define SMEM_SZ 61440   // 4 stages

// ---------------- helpers ----------------
__device__ __forceinline__ uint32_t smem_u32(const void* p) {
    uint32_t a; asm("{ .reg .u64 t; cvta.to.shared.u64 t, %1; cvt.u32.u64 %0, t; }" : "=r"(a) : "l"(p));
    return a;
}
__device__ __forceinline__ void cp16(uint32_t d, const void* s) {
    asm volatile("cp.async.cg.shared.global [%0], [%1], 16;" :: "r"(d), "l"(s));
}
__device__ __forceinline__ void ldmx4(uint32_t* r, uint32_t a) {
    asm volatile("ldmatrix.sync.aligned.m8n8.x4.shared.b16 {%0,%1,%2,%3}, [%4];"
        : "=r"(r[0]), "=r"(r[1]), "=r"(r[2]), "=r"(r[3]) : "r"(a));
}
__device__ __forceinline__ void mma_h(float* d, const uint32_t* a, const uint32_t* b) {
    asm volatile("mma.sync.aligned.m16n8k16.row.col.f32.f16.f16.f32 "
        "{%0,%1,%2,%3}, {%4,%5,%6,%7}, {%8,%9}, {%0,%1,%2,%3};"
        : "+f"(d[0]), "+f"(d[1]), "+f"(d[2]), "+f"(d[3])
        : "r"(a[0]), "r"(a[1]), "r"(a[2]), "r"(a[3]), "r"(b[0]), "r"(b[1]));
}
__device__ __forceinline__ float gatedact(float f, float g) {
    float ef = __expf(2.0f * f);
    float tf = __fdividef(ef - 1.0f, ef + 1.0f);
    float sg = __fdividef(1.0f, 1.0f + __expf(-g));
    return tf * sg;
}

// ---------------------------------------------------------------------------
// Weights: g_w1[nb][n'][k]: n'<64 filter ch nb*64+n', n'>=64 gate;
//   k<256 -> tap1 (pairs x[t]), k>=256 -> tap0 (pairs x[t-8]).
// g_w2[nb][n'][k]: n'<64 res, else skip.
// ---------------------------------------------------------------------------
__global__ void pack_w_kernel(const float* __restrict__ wf, const float* __restrict__ wg,
                              const float* __restrict__ wr, const float* __restrict__ wsk)
{
    int idx = blockIdx.x * blockDim.x + threadIdx.x;
    if (idx < 262144) {
        int nb = idx >> 16, np = (idx >> 9) & 127, k = idx & 511;
        int o = nb * 64 + (np & 63), c = k & 255;
        const float* w = (np < 64) ? wf : wg;
        g_w1[idx] = __float2half_rn(w[o * 512 + c * 2 + ((k < 256) ? 1 : 0)]);
    } else if (idx < 393216) {
        int j = idx - 262144;
        int nb = j >> 15, np = (j >> 8) & 127, k = j & 255;
        int o = nb * 64 + (np & 63);
        g_w2[j] = __float2half_rn((np < 64) ? wr[o * 256 + k] : wsk[o * 256 + k]);
    }
}

// ---------------------------------------------------------------------------
// x -> [b][r=t+8][256] fp16 plane (rows 0-7 zero). grid(64,4,16).
// ---------------------------------------------------------------------------
__global__ void pack_x_kernel(const float* __restrict__ x)
{
    __shared__ float st[64][65];
    int tc = blockIdx.x, cc = blockIdx.y, b = blockIdx.z, tid = threadIdx.x;
    for (int i = tid; i < 64 * 16; i += 256) {
        int c = i >> 4, q = i & 15;
        float4 v = *(const float4*)(x + ((size_t)(b * CHN + cc * 64 + c)) * TDIM + tc * 64 + q * 4);
        st[q*4+0][c] = v.x; st[q*4+1][c] = v.y; st[q*4+2][c] = v.z; st[q*4+3][c] = v.w;
    }
    __syncthreads();
    for (int i = tid; i < 64 * 32; i += 256) {
        int r = i >> 5, cp = (i & 31) * 2;
        __half h0 = __float2half_rn(st[r][cp]), h1 = __float2half_rn(st[r][cp + 1]);
        size_t go = ((size_t)b * 4104 + tc * 64 + 8 + r) * CHN + cc * 64 + cp;
        *(uint32_t*)(g_x + go) = ((uint32_t)__half_as_ushort(h1) << 16) | __half_as_ushort(h0);
    }
    if (tc == 0)
        for (int i = tid; i < 8 * 32; i += 256) {
            int r = i >> 5, cp = (i & 31) * 2;
            *(uint32_t*)(g_x + ((size_t)b * 4104 + r) * CHN + cc * 64 + cp) = 0;
        }
}

// ---------------------------------------------------------------------------
// GEMM: C[64 t][128 n] = A[t][K] * B[n][K]^T, single-pass fp16.
// PHASE 1: B n-tiles interleaved {f, g} -> in-register pairing, direct z stores.
// PHASE 2: direct register epilogue, 32B-sector STG.32 scatter (res/skip split
//          is warp-uniform: wn<2 res, wn>=2 skip).
// 8 warps (2m x 4n), warp tile 32x32, 4-stage ring, 3 CTAs/SM.
// ---------------------------------------------------------------------------
template<int PHASE>
__global__ void __launch_bounds__(256, 3) gemm_tc(
    const float* __restrict__ x, const float* __restrict__ b0v,
    const float* __restrict__ b1v, float* __restrict__ out)
{
    extern __shared__ unsigned char smraw[];
    const uint32_t sb = smem_u32(smraw);
    const int tid = threadIdx.x, lane = tid & 31, wid = tid >> 5;
    const int wm = wid & 1, wn = wid >> 1;
    const int tt = blockIdx.x, nb = blockIdx.y, b = blockIdx.z;
    const int t0 = tt * 64;
    const int NK  = (PHASE == 1) ? 16 : 8;
    const int KST = (PHASE == 1) ? 512 : 256;

    const __half* Ap = (PHASE == 1) ? g_x + (size_t)b * 4104 * CHN
                                    : g_z + (size_t)b * TDIM * CHN;
    const __half* Bw = (PHASE == 1) ? g_w1 + nb * 128 * 512 : g_w2 + nb * 128 * 256;

    float acc[2][4][4];
    #pragma unroll
    for (int mi = 0; mi < 2; mi++)
        #pragma unroll
        for (int ni = 0; ni < 4; ni++)
            #pragma unroll
            for (int j = 0; j < 4; j++) acc[mi][ni][j] = 0.0f;

    auto load_stage = [&](int kc, int stg) {
        int koff = (PHASE == 1 && kc < 8) ? 8 : 0;
        int acol = (PHASE == 1) ? (kc & 7) * 32 : kc * 32;
        uint32_t sbase = sb + stg * STG;
        #pragma unroll
        for (int i = 0; i < 3; i++) {
            int idx = tid + i * 256;
            if (idx < 256) {
                int r = idx >> 2, seg = idx & 3;
                const __half* asrc = Ap + (size_t)(t0 + r + koff) * CHN + acol + seg * 8;
                cp16(sbase + r * 80 + seg * 16, asrc);
            } else {
                int j = idx - 256;
                int r = j >> 2, seg = j & 3;
                const __half* bsrc = Bw + (size_t)r * KST + kc * 32 + seg * 8;
                cp16(sbase + ASTG + r * 80 + seg * 16, bsrc);
            }
        }
        asm volatile("cp.async.commit_group;" ::: "memory");
    };

    load_stage(0, 0);
    load_stage(1, 1);
    load_stage(2, 2);

    int stg = 0;
    for (int kc = 0; kc < NK; kc++) {
        int rem = NK - 1 - kc;
        if (rem >= 2)      asm volatile("cp.async.wait_group 2;" ::: "memory");
        else if (rem == 1) asm volatile("cp.async.wait_group 1;" ::: "memory");
        else               asm volatile("cp.async.wait_group 0;" ::: "memory");
        __syncthreads();

        if (kc + 3 < NK) {
            int nstg = stg + 3; if (nstg >= NSTG) nstg -= NSTG;
            load_stage(kc + 3, nstg);
        }

        const uint32_t abase = sb + stg * STG;
        const uint32_t bbase = abase + ASTG;
        #pragma unroll
        for (int ks = 0; ks < 2; ks++) {
            uint32_t ah[2][4], bf2[4][2];
            const int arow = lane & 15, acoll = ks * 16 + (lane >> 4) * 8;
            const int brow = (lane & 7) + ((lane >> 4) << 3);
            const int bcol = ks * 16 + ((lane >> 3) & 1) * 8;
            #pragma unroll
            for (int ni2 = 0; ni2 < 2; ni2++) {
                // PHASE 1: ni2=0 -> filter rows wn*16.., ni2=1 -> gate rows 64+wn*16..
                int nbase = (PHASE == 1) ? (ni2 * 64 + wn * 16) : (wn * 32 + ni2 * 16);
                uint32_t t4[4];
                ldmx4(t4, bbase + (nbase + brow) * 80 + bcol * 2);
                bf2[ni2*2][0] = t4[0]; bf2[ni2*2][1] = t4[1];
                bf2[ni2*2+1][0] = t4[2]; bf2[ni2*2+1][1] = t4[3];
            }
            #pragma unroll
            for (int mi = 0; mi < 2; mi++)
                ldmx4(ah[mi], abase + (wm * 32 + mi * 16 + arow) * 80 + acoll * 2);
            #pragma unroll
            for (int mi = 0; mi < 2; mi++)
                #pragma unroll
                for (int ni = 0; ni < 4; ni++)
                    mma_h(acc[mi][ni], ah[mi], bf2[ni]);
        }
        stg++; if (stg >= NSTG) stg = 0;
    }

    if (PHASE == 1) {
        // ---- in-register f/g pairing: acc[mi][ni] = f, acc[mi][ni+2] = g ----
        const int r0 = t0 + wm * 32 + (lane >> 2);
        float bfv[2][2], bgv[2][2];
        #pragma unroll
        for (int ni = 0; ni < 2; ni++) {
            int c = nb * 64 + wn * 16 + ni * 8 + (lane & 3) * 2;
            bfv[ni][0] = __ldg(b0v + c); bfv[ni][1] = __ldg(b0v + c + 1);
            bgv[ni][0] = __ldg(b1v + c); bgv[ni][1] = __ldg(b1v + c + 1);
        }
        #pragma unroll
        for (int mi = 0; mi < 2; mi++)
            #pragma unroll
            for (int ni = 0; ni < 2; ni++) {
                int c = nb * 64 + wn * 16 + ni * 8 + (lane & 3) * 2;
                #pragma unroll
                for (int h = 0; h < 2; h++) {
                    float f0 = acc[mi][ni][h*2]       + bfv[ni][0];
                    float f1 = acc[mi][ni][h*2 + 1]   + bfv[ni][1];
                    float g0 = acc[mi][ni+2][h*2]     + bgv[ni][0];
                    float g1 = acc[mi][ni+2][h*2 + 1] + bgv[ni][1];
                    __half h0 = __float2half_rn(gatedact(f0, g0));
                    __half h1 = __float2half_rn(gatedact(f1, g1));
                    size_t go = ((size_t)(b * TDIM + r0 + mi * 16 + h * 8)) * CHN + c;
                    *(uint32_t*)(g_z + go) =
                        ((uint32_t)__half_as_ushort(h1) << 16) | __half_as_ushort(h0);
                }
            }
    } else {
        // ---- direct register epilogue: 32B-sector STG.32 scatter ----
        // thread rows: t = t0 + wm*32 + mi*16 + (lane>>2) + h*8 (8 consecutive t
        // per lane-group = one full 32B sector per channel). Channels:
        // n' = wn*32 + ni*8 + (lane&3)*2 + {0,1}; wn<2 -> res (+x), wn>=2 -> skip.
        const int rbase = t0 + wm * 32 + (lane >> 2);
        const bool is_res = (wn < 2);
        float bias[4][2];
        #pragma unroll
        for (int ni = 0; ni < 4; ni++) {
            int np = wn * 32 + ni * 8 + (lane & 3) * 2;
            int c = nb * 64 + (is_res ? np : np - 64);
            bias[ni][0] = is_res ? __ldg(b0v + c) : __ldg(b1v + c);
            bias[ni][1] = is_res ? __ldg(b0v + c + 1) : __ldg(b1v + c + 1);
        }
        #pragma unroll
        for (int mi = 0; mi < 2; mi++)
            #pragma unroll
            for (int ni = 0; ni < 4; ni++) {
                int np = wn * 32 + ni * 8 + (lane & 3) * 2;
                int c = nb * 64 + (is_res ? np : np - 64);
                #pragma unroll
                for (int h = 0; h < 2; h++) {
                    int t = rbase + mi * 16 + h * 8;
                    size_t g0 = ((size_t)(b * CHN + c)) * TDIM + t;
                    size_t g1 = g0 + TDIM;            // channel c+1
                    float v0 = acc[mi][ni][h*2]     + bias[ni][0];
                    float v1 = acc[mi][ni][h*2 + 1] + bias[ni][1];
                    if (is_res) {
                        out[g0] = v0 + __ldg(x + g0);
                        out[g1] = v1 + __ldg(x + g1);
                    } else {
                        out[SKIPOFF + g0] = v0;
                        out[SKIPOFF + g1] = v1;
                    }
                }
            }
    }
}

// ---------------------------------------------------------------------------
extern "C" void kernel_launch(void* const* d_in, const int* in_sizes, int n_in,
                              void* d_out, int out_size)
{
    const float* x   = (const float*)d_in[0];
    const float* wf  = (const float*)d_in[1];
    const float* bf  = (const float*)d_in[2];
    const float* wg  = (const float*)d_in[3];
    const float* bg  = (const float*)d_in[4];
    const float* wr  = (const float*)d_in[5];
    const float* br  = (const float*)d_in[6];
    const float* wsk = (const float*)d_in[7];
    const float* bsk = (const float*)d_in[8];
    float* out = (float*)d_out;

    cudaFuncSetAttribute(gemm_tc<1>, cudaFuncAttributeMaxDynamicSharedMemorySize, SMEM_SZ);
    cudaFuncSetAttribute(gemm_tc<2>, cudaFuncAttributeMaxDynamicSharedMemorySize, SMEM_SZ);

    pack_w_kernel<<<1536, 256>>>(wf, wg, wr, wsk);
    pack_x_kernel<<<dim3(64, 4, BATCH), 256>>>(x);
    dim3 grid(64, 4, BATCH);
    gemm_tc<1><<<grid, 256, SMEM_SZ>>>(x, bf, bg, out);
    gemm_tc<2><<<grid, 256, SMEM_SZ>>>(x, br, bsk, out);
}

// round 13
// speedup vs baseline: 1.0747x; 1.0747x over previous
#include <cuda_runtime.h>
#include <cuda_fp16.h>
#include <cstdint>
#include <math.h>

#define CHN 256
#define TDIM 4096
#define BATCH 16
#define SKIPOFF ((size_t)BATCH*CHN*TDIM)

// single fp16 planes (device globals: allocation-free)
__device__ __half g_x[(size_t)BATCH*4104*CHN];
__device__ __half g_z[(size_t)BATCH*TDIM*CHN];
__device__ __half g_w1[4*128*512];   // tap-interleaved: k' = kc*64 + tap*32 + ki
__device__ __half g_w2[4*128*256];

// phase-1 stage: A 72 rows x 80B | B 128 rows x 144B
#define P1_STG   24192
#define P1_BOFF  5760
#define P1_SMEM  72576   // 3 stages
// phase-2 stage: A 64 rows x 80B | B 128 rows x 80B
#define P2_ASTG  5120
#define P2_STG   15360
#define P2_SMEM  61440   // 4 stages; C staging (128*68*4=34816) reuses region

// ---------------- helpers ----------------
__device__ __forceinline__ uint32_t smem_u32(const void* p) {
    uint32_t a; asm("{ .reg .u64 t; cvta.to.shared.u64 t, %1; cvt.u32.u64 %0, t; }" : "=r"(a) : "l"(p));
    return a;
}
__device__ __forceinline__ void cp16(uint32_t d, const void* s) {
    asm volatile("cp.async.cg.shared.global [%0], [%1], 16;" :: "r"(d), "l"(s));
}
__device__ __forceinline__ void ldmx4(uint32_t* r, uint32_t a) {
    asm volatile("ldmatrix.sync.aligned.m8n8.x4.shared.b16 {%0,%1,%2,%3}, [%4];"
        : "=r"(r[0]), "=r"(r[1]), "=r"(r[2]), "=r"(r[3]) : "r"(a));
}
__device__ __forceinline__ void mma_h(float* d, const uint32_t* a, const uint32_t* b) {
    asm volatile("mma.sync.aligned.m16n8k16.row.col.f32.f16.f16.f32 "
        "{%0,%1,%2,%3}, {%4,%5,%6,%7}, {%8,%9}, {%0,%1,%2,%3};"
        : "+f"(d[0]), "+f"(d[1]), "+f"(d[2]), "+f"(d[3])
        : "r"(a[0]), "r"(a[1]), "r"(a[2]), "r"(a[3]), "r"(b[0]), "r"(b[1]));
}
__device__ __forceinline__ float gatedact(float f, float g) {
    float ef = __expf(2.0f * f);
    float tf = __fdividef(ef - 1.0f, ef + 1.0f);
    float sg = __fdividef(1.0f, 1.0f + __expf(-g));
    return tf * sg;
}

// ---------------------------------------------------------------------------
// Merged packing. Blocks [0,1536): weights; [1536, 1536+4096): x plane.
// g_w1[nb][n'][k']: n'<64 filter ch nb*64+n', n'>=64 gate;
//   k' = kc*64 + tap*32 + ki, c = kc*32+ki; tap=0 -> pairs x[t] (orig tap 1),
//   tap=1 -> pairs x[t-8] (orig tap 0).
// g_w2[nb][n'][k]: n'<64 res, else skip.
// g_x: [b][r=t+8][256] fp16 (rows 0-7 zero).
// ---------------------------------------------------------------------------
__global__ void pack_all_kernel(const float* __restrict__ x,
                                const float* __restrict__ wf, const float* __restrict__ wg,
                                const float* __restrict__ wr, const float* __restrict__ wsk)
{
    int bid = blockIdx.x, tid = threadIdx.x;
    if (bid < 1536) {
        int idx = bid * 256 + tid;
        if (idx < 262144) {
            int nb = idx >> 16, np = (idx >> 9) & 127, kp = idx & 511;
            int kc = kp >> 6, tap = (kp >> 5) & 1, ki = kp & 31;
            int c = kc * 32 + ki, o = nb * 64 + (np & 63);
            const float* w = (np < 64) ? wf : wg;
            g_w1[idx] = __float2half_rn(w[o * 512 + c * 2 + (tap ? 0 : 1)]);
        } else {
            int j = idx - 262144;
            int nb = j >> 15, np = (j >> 8) & 127, k = j & 255;
            int o = nb * 64 + (np & 63);
            g_w2[j] = __float2half_rn((np < 64) ? wr[o * 256 + k] : wsk[o * 256 + k]);
        }
        return;
    }
    // ---- x pack ----
    __shared__ float st[64][65];
    int bp = bid - 1536;
    int tc = bp & 63, cc = (bp >> 6) & 3, b = bp >> 8;
    for (int i = tid; i < 64 * 16; i += 256) {
        int c = i >> 4, q = i & 15;
        float4 v = *(const float4*)(x + ((size_t)(b * CHN + cc * 64 + c)) * TDIM + tc * 64 + q * 4);
        st[q*4+0][c] = v.x; st[q*4+1][c] = v.y; st[q*4+2][c] = v.z; st[q*4+3][c] = v.w;
    }
    __syncthreads();
    for (int i = tid; i < 64 * 32; i += 256) {
        int r = i >> 5, cp = (i & 31) * 2;
        __half h0 = __float2half_rn(st[r][cp]), h1 = __float2half_rn(st[r][cp + 1]);
        size_t go = ((size_t)b * 4104 + tc * 64 + 8 + r) * CHN + cc * 64 + cp;
        *(uint32_t*)(g_x + go) = ((uint32_t)__half_as_ushort(h1) << 16) | __half_as_ushort(h0);
    }
    if (tc == 0)
        for (int i = tid; i < 8 * 32; i += 256) {
            int r = i >> 5, cp = (i & 31) * 2;
            *(uint32_t*)(g_x + ((size_t)b * 4104 + r) * CHN + cc * 64 + cp) = 0;
        }
}

// ---------------------------------------------------------------------------
// PHASE 1: C[64 t][128 n(f|g)] over K=256 channels x 2 taps (halo-shared A).
// 8 k-stages; per stage both taps' MMAs run from one A halo tile (72 rows).
// B n-tiles interleaved {f, g} -> in-register pairing, direct z stores.
// ---------------------------------------------------------------------------
__global__ void __launch_bounds__(256, 3) gemm_p1(
    const float* __restrict__ b0v, const float* __restrict__ b1v)
{
    extern __shared__ unsigned char smraw[];
    const uint32_t sb = smem_u32(smraw);
    const int tid = threadIdx.x, lane = tid & 31, wid = tid >> 5;
    const int wm = wid & 1, wn = wid >> 1;
    const int tt = blockIdx.x, nb = blockIdx.y, b = blockIdx.z;
    const int t0 = tt * 64;

    const __half* Ap = g_x + (size_t)b * 4104 * CHN;
    const __half* Bw = g_w1 + nb * 128 * 512;

    float acc[2][4][4];
    #pragma unroll
    for (int mi = 0; mi < 2; mi++)
        #pragma unroll
        for (int ni = 0; ni < 4; ni++)
            #pragma unroll
            for (int j = 0; j < 4; j++) acc[mi][ni][j] = 0.0f;

    auto load_stage = [&](int kc, int stg) {
        uint32_t sbase = sb + stg * P1_STG;
        #pragma unroll
        for (int i = 0; i < 6; i++) {
            int idx = tid + i * 256;
            if (idx < 288) {                      // A: 72 rows x 4 x 16B
                int r = idx >> 2, seg = idx & 3;
                const __half* asrc = Ap + (size_t)(t0 + r) * CHN + kc * 32 + seg * 8;
                cp16(sbase + r * 80 + seg * 16, asrc);
            } else if (idx < 1312) {              // B: 128 rows x 8 x 16B
                int j = idx - 288;
                int r = j >> 3, seg = j & 7;
                const __half* bsrc = Bw + (size_t)r * 512 + kc * 64 + seg * 8;
                cp16(sbase + P1_BOFF + r * 144 + seg * 16, bsrc);
            }
        }
        asm volatile("cp.async.commit_group;" ::: "memory");
    };

    load_stage(0, 0);
    load_stage(1, 1);

    int stg = 0;
    for (int kc = 0; kc < 8; kc++) {
        if (kc < 7) asm volatile("cp.async.wait_group 1;" ::: "memory");
        else        asm volatile("cp.async.wait_group 0;" ::: "memory");
        __syncthreads();
        if (kc + 2 < 8) {
            int nstg = stg + 2; if (nstg >= 3) nstg -= 3;
            load_stage(kc + 2, nstg);
        }

        const uint32_t abase = sb + stg * P1_STG;
        const uint32_t bbase = abase + P1_BOFF;
        #pragma unroll
        for (int tap = 0; tap < 2; tap++) {
            const int arowoff = tap ? 0 : 8;      // tap0 pairs x[t] (+8), tap1 x[t-8]
            #pragma unroll
            for (int ks = 0; ks < 2; ks++) {
                uint32_t ah[2][4], bf2[4][2];
                const int arow = lane & 15, acoll = ks * 16 + (lane >> 4) * 8;
                const int brow = (lane & 7) + ((lane >> 4) << 3);
                const int bcol = ks * 16 + ((lane >> 3) & 1) * 8;
                #pragma unroll
                for (int ni2 = 0; ni2 < 2; ni2++) {
                    int nbase = ni2 * 64 + wn * 16;   // f rows / g rows
                    uint32_t t4[4];
                    ldmx4(t4, bbase + (nbase + brow) * 144 + tap * 64 + bcol * 2);
                    bf2[ni2*2][0] = t4[0]; bf2[ni2*2][1] = t4[1];
                    bf2[ni2*2+1][0] = t4[2]; bf2[ni2*2+1][1] = t4[3];
                }
                #pragma unroll
                for (int mi = 0; mi < 2; mi++)
                    ldmx4(ah[mi], abase + (arowoff + wm * 32 + mi * 16 + arow) * 80 + acoll * 2);
                #pragma unroll
                for (int mi = 0; mi < 2; mi++)
                    #pragma unroll
                    for (int ni = 0; ni < 4; ni++)
                        mma_h(acc[mi][ni], ah[mi], bf2[ni]);
            }
        }
        stg++; if (stg >= 3) stg = 0;
    }

    // ---- in-register f/g pairing epilogue: acc[mi][ni]=f, acc[mi][ni+2]=g ----
    const int r0 = t0 + wm * 32 + (lane >> 2);
    float bfv[2][2], bgv[2][2];
    #pragma unroll
    for (int ni = 0; ni < 2; ni++) {
        int c = nb * 64 + wn * 16 + ni * 8 + (lane & 3) * 2;
        bfv[ni][0] = __ldg(b0v + c); bfv[ni][1] = __ldg(b0v + c + 1);
        bgv[ni][0] = __ldg(b1v + c); bgv[ni][1] = __ldg(b1v + c + 1);
    }
    #pragma unroll
    for (int mi = 0; mi < 2; mi++)
        #pragma unroll
        for (int ni = 0; ni < 2; ni++) {
            int c = nb * 64 + wn * 16 + ni * 8 + (lane & 3) * 2;
            #pragma unroll
            for (int h = 0; h < 2; h++) {
                float f0 = acc[mi][ni][h*2]       + bfv[ni][0];
                float f1 = acc[mi][ni][h*2 + 1]   + bfv[ni][1];
                float g0 = acc[mi][ni+2][h*2]     + bgv[ni][0];
                float g1 = acc[mi][ni+2][h*2 + 1] + bgv[ni][1];
                __half h0 = __float2half_rn(gatedact(f0, g0));
                __half h1 = __float2half_rn(gatedact(f1, g1));
                size_t go = ((size_t)(b * TDIM + r0 + mi * 16 + h * 8)) * CHN + c;
                *(uint32_t*)(g_z + go) =
                    ((uint32_t)__half_as_ushort(h1) << 16) | __half_as_ushort(h0);
            }
        }
}

// ---------------------------------------------------------------------------
// PHASE 2: C[64 t][128 n(res|skip)] = z * W2^T, K=256; smem C transpose staging.
// ---------------------------------------------------------------------------
__global__ void __launch_bounds__(256, 3) gemm_p2(
    const float* __restrict__ x, const float* __restrict__ b0v,
    const float* __restrict__ b1v, float* __restrict__ out)
{
    extern __shared__ unsigned char smraw[];
    const uint32_t sb = smem_u32(smraw);
    const int tid = threadIdx.x, lane = tid & 31, wid = tid >> 5;
    const int wm = wid & 1, wn = wid >> 1;
    const int tt = blockIdx.x, nb = blockIdx.y, b = blockIdx.z;
    const int t0 = tt * 64;

    const __half* Ap = g_z + (size_t)b * TDIM * CHN;
    const __half* Bw = g_w2 + nb * 128 * 256;

    float acc[2][4][4];
    #pragma unroll
    for (int mi = 0; mi < 2; mi++)
        #pragma unroll
        for (int ni = 0; ni < 4; ni++)
            #pragma unroll
            for (int j = 0; j < 4; j++) acc[mi][ni][j] = 0.0f;

    auto load_stage = [&](int kc, int stg) {
        uint32_t sbase = sb + stg * P2_STG;
        #pragma unroll
        for (int i = 0; i < 3; i++) {
            int idx = tid + i * 256;
            if (idx < 256) {
                int r = idx >> 2, seg = idx & 3;
                const __half* asrc = Ap + (size_t)(t0 + r) * CHN + kc * 32 + seg * 8;
                cp16(sbase + r * 80 + seg * 16, asrc);
            } else {
                int j = idx - 256;
                int r = j >> 2, seg = j & 3;
                const __half* bsrc = Bw + (size_t)r * 256 + kc * 32 + seg * 8;
                cp16(sbase + P2_ASTG + r * 80 + seg * 16, bsrc);
            }
        }
        asm volatile("cp.async.commit_group;" ::: "memory");
    };

    load_stage(0, 0);
    load_stage(1, 1);
    load_stage(2, 2);

    int stg = 0;
    for (int kc = 0; kc < 8; kc++) {
        int rem = 7 - kc;
        if (rem >= 2)      asm volatile("cp.async.wait_group 2;" ::: "memory");
        else if (rem == 1) asm volatile("cp.async.wait_group 1;" ::: "memory");
        else               asm volatile("cp.async.wait_group 0;" ::: "memory");
        __syncthreads();
        if (kc + 3 < 8) {
            int nstg = stg + 3; if (nstg >= 4) nstg -= 4;
            load_stage(kc + 3, nstg);
        }

        const uint32_t abase = sb + stg * P2_STG;
        const uint32_t bbase = abase + P2_ASTG;
        #pragma unroll
        for (int ks = 0; ks < 2; ks++) {
            uint32_t ah[2][4], bf2[4][2];
            const int arow = lane & 15, acoll = ks * 16 + (lane >> 4) * 8;
            const int brow = (lane & 7) + ((lane >> 4) << 3);
            const int bcol = ks * 16 + ((lane >> 3) & 1) * 8;
            #pragma unroll
            for (int ni2 = 0; ni2 < 2; ni2++) {
                int nbase = wn * 32 + ni2 * 16;
                uint32_t t4[4];
                ldmx4(t4, bbase + (nbase + brow) * 80 + bcol * 2);
                bf2[ni2*2][0] = t4[0]; bf2[ni2*2][1] = t4[1];
                bf2[ni2*2+1][0] = t4[2]; bf2[ni2*2+1][1] = t4[3];
            }
            #pragma unroll
            for (int mi = 0; mi < 2; mi++)
                ldmx4(ah[mi], abase + (wm * 32 + mi * 16 + arow) * 80 + acoll * 2);
            #pragma unroll
            for (int mi = 0; mi < 2; mi++)
                #pragma unroll
                for (int ni = 0; ni < 4; ni++)
                    mma_h(acc[mi][ni], ah[mi], bf2[ni]);
        }
        stg++; if (stg >= 4) stg = 0;
    }
    __syncthreads();

    // ---- stage C through smem [128 n][68 m] for t-major output ----
    float* Cs = (float*)smraw;
    {
        const int tr = lane >> 2, tc4 = (lane & 3) * 2;
        #pragma unroll
        for (int mi = 0; mi < 2; mi++)
            #pragma unroll
            for (int ni = 0; ni < 4; ni++) {
                int n0 = wn * 32 + ni * 8 + tc4;
                int m0 = wm * 32 + mi * 16 + tr;
                Cs[n0 * 68 + m0]           = acc[mi][ni][0];
                Cs[(n0 + 1) * 68 + m0]     = acc[mi][ni][1];
                Cs[n0 * 68 + m0 + 8]       = acc[mi][ni][2];
                Cs[(n0 + 1) * 68 + m0 + 8] = acc[mi][ni][3];
            }
    }
    __syncthreads();

    for (int i = tid; i < 128 * 16; i += 256) {
        int c1 = i >> 4, mp = (i & 15) * 4;
        size_t go = ((size_t)(b * CHN + nb * 64 + ((c1 < 64) ? c1 : c1 - 64))) * TDIM + t0 + mp;
        if (c1 < 64) {
            float bias = __ldg(b0v + nb * 64 + c1);
            float4 xv = *(const float4*)(x + go);
            float4 v = make_float4(Cs[c1*68+mp]   + bias + xv.x,
                                   Cs[c1*68+mp+1] + bias + xv.y,
                                   Cs[c1*68+mp+2] + bias + xv.z,
                                   Cs[c1*68+mp+3] + bias + xv.w);
            *(float4*)(out + go) = v;
        } else {
            float bias = __ldg(b1v + nb * 64 + (c1 - 64));
            float4 v = make_float4(Cs[c1*68+mp]   + bias,
                                   Cs[c1*68+mp+1] + bias,
                                   Cs[c1*68+mp+2] + bias,
                                   Cs[c1*68+mp+3] + bias);
            *(float4*)(out + SKIPOFF + go) = v;
        }
    }
}

// ---------------------------------------------------------------------------
extern "C" void kernel_launch(void* const* d_in, const int* in_sizes, int n_in,
                              void* d_out, int out_size)
{
    const float* x   = (const float*)d_in[0];
    const float* wf  = (const float*)d_in[1];
    const float* bf  = (const float*)d_in[2];
    const float* wg  = (const float*)d_in[3];
    const float* bg  = (const float*)d_in[4];
    const float* wr  = (const float*)d_in[5];
    const float* br  = (const float*)d_in[6];
    const float* wsk = (const float*)d_in[7];
    const float* bsk = (const float*)d_in[8];
    float* out = (float*)d_out;

    cudaFuncSetAttribute(gemm_p1, cudaFuncAttributeMaxDynamicSharedMemorySize, P1_SMEM);
    cudaFuncSetAttribute(gemm_p2, cudaFuncAttributeMaxDynamicSharedMemorySize, P2_SMEM);

    pack_all_kernel<<<1536 + 4096, 256>>>(x, wf, wg, wr, wsk);
    dim3 grid(64, 4, BATCH);
    gemm_p1<<<grid, 256, P1_SMEM>>>(bf, bg);
    gemm_p2<<<grid, 256, P2_SMEM>>>(x, br, bsk, out);
}

// round 14
// speedup vs baseline: 1.6751x; 1.5587x over previous
#include <cuda_runtime.h>
#include <cuda_fp16.h>
#include <cstdint>
#include <math.h>

#define CHN 256
#define TDIM 4096
#define BATCH 16
#define SKIPOFF ((size_t)BATCH*CHN*TDIM)

// single fp16 planes (device globals: allocation-free)
__device__ __half g_x[(size_t)BATCH*4104*CHN];
__device__ __half g_z[(size_t)BATCH*TDIM*CHN];
__device__ __half g_w1[4*128*512];
__device__ __half g_w2[4*128*256];

// A persistent buffers (pitch 528 B = 264 half) + B-only stage rings (128 rows x 80B)
#define APITCH  528
#define P1_ABUF 38016            // 72 rows
#define P2_ABUF 33792            // 64 rows
#define BSTG    10240
#define P1_SMEM (P1_ABUF + 3*BSTG)   // 68736, ring 3
#define P2_SMEM (P2_ABUF + 4*BSTG)   // 74752, ring 4; C staging (34816) reuses front

// ---------------- helpers ----------------
__device__ __forceinline__ uint32_t smem_u32(const void* p) {
    uint32_t a; asm("{ .reg .u64 t; cvta.to.shared.u64 t, %1; cvt.u32.u64 %0, t; }" : "=r"(a) : "l"(p));
    return a;
}
__device__ __forceinline__ void cp16(uint32_t d, const void* s) {
    asm volatile("cp.async.cg.shared.global [%0], [%1], 16;" :: "r"(d), "l"(s));
}
__device__ __forceinline__ void ldmx4(uint32_t* r, uint32_t a) {
    asm volatile("ldmatrix.sync.aligned.m8n8.x4.shared.b16 {%0,%1,%2,%3}, [%4];"
        : "=r"(r[0]), "=r"(r[1]), "=r"(r[2]), "=r"(r[3]) : "r"(a));
}
__device__ __forceinline__ void mma_h(float* d, const uint32_t* a, const uint32_t* b) {
    asm volatile("mma.sync.aligned.m16n8k16.row.col.f32.f16.f16.f32 "
        "{%0,%1,%2,%3}, {%4,%5,%6,%7}, {%8,%9}, {%0,%1,%2,%3};"
        : "+f"(d[0]), "+f"(d[1]), "+f"(d[2]), "+f"(d[3])
        : "r"(a[0]), "r"(a[1]), "r"(a[2]), "r"(a[3]), "r"(b[0]), "r"(b[1]));
}
__device__ __forceinline__ float gatedact(float f, float g) {
    float ef = __expf(2.0f * f);
    float tf = __fdividef(ef - 1.0f, ef + 1.0f);
    float sg = __fdividef(1.0f, 1.0f + __expf(-g));
    return tf * sg;
}

// ---------------------------------------------------------------------------
// Merged packing. Blocks [0,1536): weights; [1536,1536+4096): x plane.
// g_w1[nb][n'][k]: n'<64 filter ch nb*64+n', n'>=64 gate;
//   k<256 -> tap1 (pairs x[t]), k>=256 -> tap0 (pairs x[t-8]).   (R11 layout)
// g_w2[nb][n'][k]: n'<64 res, else skip.
// g_x: [b][r=t+8][256] fp16 (rows 0-7 zero).
// ---------------------------------------------------------------------------
__global__ void pack_all_kernel(const float* __restrict__ x,
                                const float* __restrict__ wf, const float* __restrict__ wg,
                                const float* __restrict__ wr, const float* __restrict__ wsk)
{
    int bid = blockIdx.x, tid = threadIdx.x;
    if (bid < 1536) {
        int idx = bid * 256 + tid;
        if (idx < 262144) {
            int nb = idx >> 16, np = (idx >> 9) & 127, k = idx & 511;
            int o = nb * 64 + (np & 63), c = k & 255;
            const float* w = (np < 64) ? wf : wg;
            g_w1[idx] = __float2half_rn(w[o * 512 + c * 2 + ((k < 256) ? 1 : 0)]);
        } else {
            int j = idx - 262144;
            int nb = j >> 15, np = (j >> 8) & 127, k = j & 255;
            int o = nb * 64 + (np & 63);
            g_w2[j] = __float2half_rn((np < 64) ? wr[o * 256 + k] : wsk[o * 256 + k]);
        }
        return;
    }
    __shared__ float st[64][65];
    int bp = bid - 1536;
    int tc = bp & 63, cc = (bp >> 6) & 3, b = bp >> 8;
    for (int i = tid; i < 64 * 16; i += 256) {
        int c = i >> 4, q = i & 15;
        float4 v = *(const float4*)(x + ((size_t)(b * CHN + cc * 64 + c)) * TDIM + tc * 64 + q * 4);
        st[q*4+0][c] = v.x; st[q*4+1][c] = v.y; st[q*4+2][c] = v.z; st[q*4+3][c] = v.w;
    }
    __syncthreads();
    for (int i = tid; i < 64 * 32; i += 256) {
        int r = i >> 5, cp = (i & 31) * 2;
        __half h0 = __float2half_rn(st[r][cp]), h1 = __float2half_rn(st[r][cp + 1]);
        size_t go = ((size_t)b * 4104 + tc * 64 + 8 + r) * CHN + cc * 64 + cp;
        *(uint32_t*)(g_x + go) = ((uint32_t)__half_as_ushort(h1) << 16) | __half_as_ushort(h0);
    }
    if (tc == 0)
        for (int i = tid; i < 8 * 32; i += 256) {
            int r = i >> 5, cp = (i & 31) * 2;
            *(uint32_t*)(g_x + ((size_t)b * 4104 + r) * CHN + cc * 64 + cp) = 0;
        }
}

// ---------------------------------------------------------------------------
// PHASE 1: C[64 t][128 n(f|g)], K=512. A persistent (72 rows x 256 ch, both taps
// share the buffer via +8 row offset). B-only 3-stage ring. In-register f/g
// pairing epilogue, direct z stores.  (mainloop math identical to R11)
// ---------------------------------------------------------------------------
__global__ void __launch_bounds__(256, 3) gemm_p1(
    const float* __restrict__ b0v, const float* __restrict__ b1v)
{
    extern __shared__ unsigned char smraw[];
    const uint32_t sb = smem_u32(smraw);
    const int tid = threadIdx.x, lane = tid & 31, wid = tid >> 5;
    const int wm = wid & 1, wn = wid >> 1;
    const int tt = blockIdx.x, nb = blockIdx.y, b = blockIdx.z;
    const int t0 = tt * 64;

    const __half* Ap = g_x + (size_t)b * 4104 * CHN;
    const __half* Bw = g_w1 + nb * 128 * 512;

    float acc[2][4][4];
    #pragma unroll
    for (int mi = 0; mi < 2; mi++)
        #pragma unroll
        for (int ni = 0; ni < 4; ni++)
            #pragma unroll
            for (int j = 0; j < 4; j++) acc[mi][ni][j] = 0.0f;

    // ---- persistent A load: 72 rows x 32 chunks (group 0) ----
    for (int i = tid; i < 72 * 32; i += 256) {
        int r = i >> 5, seg = i & 31;
        cp16(sb + r * APITCH + seg * 16, Ap + (size_t)(t0 + r) * CHN + seg * 8);
    }
    asm volatile("cp.async.commit_group;" ::: "memory");

    auto load_stage = [&](int kc, int stg) {
        uint32_t sbase = sb + P1_ABUF + stg * BSTG;
        #pragma unroll
        for (int i = 0; i < 2; i++) {
            int idx = tid + i * 256;
            int r = idx >> 2, seg = idx & 3;
            cp16(sbase + r * 80 + seg * 16, Bw + (size_t)r * 512 + kc * 32 + seg * 8);
        }
        asm volatile("cp.async.commit_group;" ::: "memory");
    };

    load_stage(0, 0);
    load_stage(1, 1);

    int stg = 0;
    for (int kc = 0; kc < 16; kc++) {
        if (kc < 15) asm volatile("cp.async.wait_group 1;" ::: "memory");
        else         asm volatile("cp.async.wait_group 0;" ::: "memory");
        __syncthreads();
        if (kc + 2 < 16) {
            int nstg = stg + 2; if (nstg >= 3) nstg -= 3;
            load_stage(kc + 2, nstg);
        }

        const int koff = (kc < 8) ? 8 : 0;       // tap: x[t] (+8) vs x[t-8]
        const int acolb = (kc & 7) * 64;          // channel byte offset
        const uint32_t bbase = sb + P1_ABUF + stg * BSTG;
        #pragma unroll
        for (int ks = 0; ks < 2; ks++) {
            uint32_t ah[2][4], bf2[4][2];
            const int arow = lane & 15, acoll = ks * 16 + (lane >> 4) * 8;
            const int brow = (lane & 7) + ((lane >> 4) << 3);
            const int bcol = ks * 16 + ((lane >> 3) & 1) * 8;
            #pragma unroll
            for (int ni2 = 0; ni2 < 2; ni2++) {
                int nbase = ni2 * 64 + wn * 16;   // f rows / g rows (interleaved pairing)
                uint32_t t4[4];
                ldmx4(t4, bbase + (nbase + brow) * 80 + bcol * 2);
                bf2[ni2*2][0] = t4[0]; bf2[ni2*2][1] = t4[1];
                bf2[ni2*2+1][0] = t4[2]; bf2[ni2*2+1][1] = t4[3];
            }
            #pragma unroll
            for (int mi = 0; mi < 2; mi++)
                ldmx4(ah[mi], sb + (koff + wm * 32 + mi * 16 + arow) * APITCH
                               + acolb + acoll * 2);
            #pragma unroll
            for (int mi = 0; mi < 2; mi++)
                #pragma unroll
                for (int ni = 0; ni < 4; ni++)
                    mma_h(acc[mi][ni], ah[mi], bf2[ni]);
        }
        stg++; if (stg >= 3) stg = 0;
    }

    // ---- in-register f/g pairing epilogue: acc[mi][ni]=f, acc[mi][ni+2]=g ----
    const int r0 = t0 + wm * 32 + (lane >> 2);
    float bfv[2][2], bgv[2][2];
    #pragma unroll
    for (int ni = 0; ni < 2; ni++) {
        int c = nb * 64 + wn * 16 + ni * 8 + (lane & 3) * 2;
        bfv[ni][0] = __ldg(b0v + c); bfv[ni][1] = __ldg(b0v + c + 1);
        bgv[ni][0] = __ldg(b1v + c); bgv[ni][1] = __ldg(b1v + c + 1);
    }
    #pragma unroll
    for (int mi = 0; mi < 2; mi++)
        #pragma unroll
        for (int ni = 0; ni < 2; ni++) {
            int c = nb * 64 + wn * 16 + ni * 8 + (lane & 3) * 2;
            #pragma unroll
            for (int h = 0; h < 2; h++) {
                float f0 = acc[mi][ni][h*2]       + bfv[ni][0];
                float f1 = acc[mi][ni][h*2 + 1]   + bfv[ni][1];
                float g0 = acc[mi][ni+2][h*2]     + bgv[ni][0];
                float g1 = acc[mi][ni+2][h*2 + 1] + bgv[ni][1];
                __half h0 = __float2half_rn(gatedact(f0, g0));
                __half h1 = __float2half_rn(gatedact(f1, g1));
                size_t go = ((size_t)(b * TDIM + r0 + mi * 16 + h * 8)) * CHN + c;
                *(uint32_t*)(g_z + go) =
                    ((uint32_t)__half_as_ushort(h1) << 16) | __half_as_ushort(h0);
            }
        }
}

// ---------------------------------------------------------------------------
// PHASE 2: C[64 t][128 n(res|skip)] = z * W2^T, K=256. A (z) persistent,
// B-only 4-stage ring, smem C transpose staging (t-major output).
// ---------------------------------------------------------------------------
__global__ void __launch_bounds__(256, 3) gemm_p2(
    const float* __restrict__ x, const float* __restrict__ b0v,
    const float* __restrict__ b1v, float* __restrict__ out)
{
    extern __shared__ unsigned char smraw[];
    const uint32_t sb = smem_u32(smraw);
    const int tid = threadIdx.x, lane = tid & 31, wid = tid >> 5;
    const int wm = wid & 1, wn = wid >> 1;
    const int tt = blockIdx.x, nb = blockIdx.y, b = blockIdx.z;
    const int t0 = tt * 64;

    const __half* Ap = g_z + (size_t)b * TDIM * CHN;
    const __half* Bw = g_w2 + nb * 128 * 256;

    float acc[2][4][4];
    #pragma unroll
    for (int mi = 0; mi < 2; mi++)
        #pragma unroll
        for (int ni = 0; ni < 4; ni++)
            #pragma unroll
            for (int j = 0; j < 4; j++) acc[mi][ni][j] = 0.0f;

    // ---- persistent A (z) load: 64 rows x 32 chunks (group 0) ----
    for (int i = tid; i < 64 * 32; i += 256) {
        int r = i >> 5, seg = i & 31;
        cp16(sb + r * APITCH + seg * 16, Ap + (size_t)(t0 + r) * CHN + seg * 8);
    }
    asm volatile("cp.async.commit_group;" ::: "memory");

    auto load_stage = [&](int kc, int stg) {
        uint32_t sbase = sb + P2_ABUF + stg * BSTG;
        #pragma unroll
        for (int i = 0; i < 2; i++) {
            int idx = tid + i * 256;
            int r = idx >> 2, seg = idx & 3;
            cp16(sbase + r * 80 + seg * 16, Bw + (size_t)r * 256 + kc * 32 + seg * 8);
        }
        asm volatile("cp.async.commit_group;" ::: "memory");
    };

    load_stage(0, 0);
    load_stage(1, 1);
    load_stage(2, 2);

    int stg = 0;
    for (int kc = 0; kc < 8; kc++) {
        int rem = 7 - kc;
        if (rem >= 2)      asm volatile("cp.async.wait_group 2;" ::: "memory");
        else if (rem == 1) asm volatile("cp.async.wait_group 1;" ::: "memory");
        else               asm volatile("cp.async.wait_group 0;" ::: "memory");
        __syncthreads();
        if (kc + 3 < 8) {
            int nstg = stg + 3; if (nstg >= 4) nstg -= 4;
            load_stage(kc + 3, nstg);
        }

        const uint32_t bbase = sb + P2_ABUF + stg * BSTG;
        #pragma unroll
        for (int ks = 0; ks < 2; ks++) {
            uint32_t ah[2][4], bf2[4][2];
            const int arow = lane & 15, acoll = ks * 16 + (lane >> 4) * 8;
            const int brow = (lane & 7) + ((lane >> 4) << 3);
            const int bcol = ks * 16 + ((lane >> 3) & 1) * 8;
            #pragma unroll
            for (int ni2 = 0; ni2 < 2; ni2++) {
                int nbase = wn * 32 + ni2 * 16;
                uint32_t t4[4];
                ldmx4(t4, bbase + (nbase + brow) * 80 + bcol * 2);
                bf2[ni2*2][0] = t4[0]; bf2[ni2*2][1] = t4[1];
                bf2[ni2*2+1][0] = t4[2]; bf2[ni2*2+1][1] = t4[3];
            }
            #pragma unroll
            for (int mi = 0; mi < 2; mi++)
                ldmx4(ah[mi], sb + (wm * 32 + mi * 16 + arow) * APITCH
                               + kc * 64 + acoll * 2);
            #pragma unroll
            for (int mi = 0; mi < 2; mi++)
                #pragma unroll
                for (int ni = 0; ni < 4; ni++)
                    mma_h(acc[mi][ni], ah[mi], bf2[ni]);
        }
        stg++; if (stg >= 4) stg = 0;
    }
    __syncthreads();

    // ---- stage C through smem [128 n][68 m] (reuses A region) ----
    float* Cs = (float*)smraw;
    {
        const int tr = lane >> 2, tc4 = (lane & 3) * 2;
        #pragma unroll
        for (int mi = 0; mi < 2; mi++)
            #pragma unroll
            for (int ni = 0; ni < 4; ni++) {
                int n0 = wn * 32 + ni * 8 + tc4;
                int m0 = wm * 32 + mi * 16 + tr;
                Cs[n0 * 68 + m0]           = acc[mi][ni][0];
                Cs[(n0 + 1) * 68 + m0]     = acc[mi][ni][1];
                Cs[n0 * 68 + m0 + 8]       = acc[mi][ni][2];
                Cs[(n0 + 1) * 68 + m0 + 8] = acc[mi][ni][3];
            }
    }
    __syncthreads();

    for (int i = tid; i < 128 * 16; i += 256) {
        int c1 = i >> 4, mp = (i & 15) * 4;
        size_t go = ((size_t)(b * CHN + nb * 64 + ((c1 < 64) ? c1 : c1 - 64))) * TDIM + t0 + mp;
        if (c1 < 64) {
            float bias = __ldg(b0v + nb * 64 + c1);
            float4 xv = *(const float4*)(x + go);
            float4 v = make_float4(Cs[c1*68+mp]   + bias + xv.x,
                                   Cs[c1*68+mp+1] + bias + xv.y,
                                   Cs[c1*68+mp+2] + bias + xv.z,
                                   Cs[c1*68+mp+3] + bias + xv.w);
            *(float4*)(out + go) = v;
        } else {
            float bias = __ldg(b1v + nb * 64 + (c1 - 64));
            float4 v = make_float4(Cs[c1*68+mp]   + bias,
                                   Cs[c1*68+mp+1] + bias,
                                   Cs[c1*68+mp+2] + bias,
                                   Cs[c1*68+mp+3] + bias);
            *(float4*)(out + SKIPOFF + go) = v;
        }
    }
}

// ---------------------------------------------------------------------------
extern "C" void kernel_launch(void* const* d_in, const int* in_sizes, int n_in,
                              void* d_out, int out_size)
{
    const float* x   = (const float*)d_in[0];
    const float* wf  = (const float*)d_in[1];
    const float* bf  = (const float*)d_in[2];
    const float* wg  = (const float*)d_in[3];
    const float* bg  = (const float*)d_in[4];
    const float* wr  = (const float*)d_in[5];
    const float* br  = (const float*)d_in[6];
    const float* wsk = (const float*)d_in[7];
    const float* bsk = (const float*)d_in[8];
    float* out = (float*)d_out;

    cudaFuncSetAttribute(gemm_p1, cudaFuncAttributeMaxDynamicSharedMemorySize, P1_SMEM);
    cudaFuncSetAttribute(gemm_p2, cudaFuncAttributeMaxDynamicSharedMemorySize, P2_SMEM);

    pack_all_kernel<<<1536 + 4096, 256>>>(x, wf, wg, wr, wsk);
    dim3 grid(64, 4, BATCH);
    gemm_p1<<<grid, 256, P1_SMEM>>>(bf, bg);
    gemm_p2<<<grid, 256, P2_SMEM>>>(x, br, bsk, out);
}

// round 15
// speedup vs baseline: 1.7366x; 1.0367x over previous
#include <cuda_runtime.h>
#include <cuda_fp16.h>
#include <cstdint>
#include <math.h>

#define CHN 256
#define TDIM 4096
#define BATCH 16
#define SKIPOFF ((size_t)BATCH*CHN*TDIM)

// single fp16 planes (device globals: allocation-free)
__device__ __half g_x[(size_t)BATCH*4104*CHN];
__device__ __half g_z[(size_t)BATCH*TDIM*CHN];
__device__ __half g_w1[4*128*512];
__device__ __half g_w2[4*128*256];

// A persistent buffers (pitch 528 B = 264 half) + B-only stage rings (128 rows x 80B)
#define APITCH  528
#define P1_ABUF 38016            // 72 rows
#define P2_ABUF 33792            // 64 rows
#define BSTG    10240
#define P1_SMEM (P1_ABUF + 3*BSTG)   // 68736, ring 3
#define P2_SMEM (P2_ABUF + 4*BSTG)   // 74752, ring 4; C staging (34816) reuses front

// ---------------- helpers ----------------
__device__ __forceinline__ uint32_t smem_u32(const void* p) {
    uint32_t a; asm("{ .reg .u64 t; cvta.to.shared.u64 t, %1; cvt.u32.u64 %0, t; }" : "=r"(a) : "l"(p));
    return a;
}
__device__ __forceinline__ void cp16(uint32_t d, const void* s) {
    asm volatile("cp.async.cg.shared.global [%0], [%1], 16;" :: "r"(d), "l"(s));
}
__device__ __forceinline__ void ldmx4(uint32_t* r, uint32_t a) {
    asm volatile("ldmatrix.sync.aligned.m8n8.x4.shared.b16 {%0,%1,%2,%3}, [%4];"
        : "=r"(r[0]), "=r"(r[1]), "=r"(r[2]), "=r"(r[3]) : "r"(a));
}
__device__ __forceinline__ void mma_h(float* d, const uint32_t* a, const uint32_t* b) {
    asm volatile("mma.sync.aligned.m16n8k16.row.col.f32.f16.f16.f32 "
        "{%0,%1,%2,%3}, {%4,%5,%6,%7}, {%8,%9}, {%0,%1,%2,%3};"
        : "+f"(d[0]), "+f"(d[1]), "+f"(d[2]), "+f"(d[3])
        : "r"(a[0]), "r"(a[1]), "r"(a[2]), "r"(a[3]), "r"(b[0]), "r"(b[1]));
}
__device__ __forceinline__ float gatedact(float f, float g) {
    float ef = __expf(2.0f * f);
    float tf = __fdividef(ef - 1.0f, ef + 1.0f);
    float sg = __fdividef(1.0f, 1.0f + __expf(-g));
    return tf * sg;
}

// ---------------------------------------------------------------------------
// Merged packing. Blocks [0,1536): weights; [1536,1536+2048): x plane (128-t
// tiles for MLP=8 on the load side).
// g_w1[nb][n'][k]: n'<64 filter ch nb*64+n', n'>=64 gate;
//   k<256 -> tap1 (pairs x[t]), k>=256 -> tap0 (pairs x[t-8]).
// g_w2[nb][n'][k]: n'<64 res, else skip.
// g_x: [b][r=t+8][256] fp16 (rows 0-7 zero).
// ---------------------------------------------------------------------------
__global__ void pack_all_kernel(const float* __restrict__ x,
                                const float* __restrict__ wf, const float* __restrict__ wg,
                                const float* __restrict__ wr, const float* __restrict__ wsk)
{
    int bid = blockIdx.x, tid = threadIdx.x;
    if (bid < 1536) {
        int idx = bid * 256 + tid;
        if (idx < 262144) {
            int nb = idx >> 16, np = (idx >> 9) & 127, k = idx & 511;
            int o = nb * 64 + (np & 63), c = k & 255;
            const float* w = (np < 64) ? wf : wg;
            g_w1[idx] = __float2half_rn(w[o * 512 + c * 2 + ((k < 256) ? 1 : 0)]);
        } else {
            int j = idx - 262144;
            int nb = j >> 15, np = (j >> 8) & 127, k = j & 255;
            int o = nb * 64 + (np & 63);
            g_w2[j] = __float2half_rn((np < 64) ? wr[o * 256 + k] : wsk[o * 256 + k]);
        }
        return;
    }
    // ---- x pack: one block = 128 t x 64 ch ----
    __shared__ float st[128][65];
    int bp = bid - 1536;
    int tc = bp & 31, cc = (bp >> 5) & 3, b = bp >> 7;
    #pragma unroll
    for (int k = 0; k < 8; k++) {             // 64 ch x 32 q, 8 iters, MLP 8
        int i = tid + k * 256;
        int c = i >> 5, q = i & 31;
        float4 v = *(const float4*)(x + ((size_t)(b * CHN + cc * 64 + c)) * TDIM + tc * 128 + q * 4);
        st[q*4+0][c] = v.x; st[q*4+1][c] = v.y; st[q*4+2][c] = v.z; st[q*4+3][c] = v.w;
    }
    __syncthreads();
    #pragma unroll
    for (int k = 0; k < 16; k++) {            // 128 rows x 32 ch-pairs
        int i = tid + k * 256;
        int r = i >> 5, cp = (i & 31) * 2;
        __half h0 = __float2half_rn(st[r][cp]), h1 = __float2half_rn(st[r][cp + 1]);
        size_t go = ((size_t)b * 4104 + tc * 128 + 8 + r) * CHN + cc * 64 + cp;
        *(uint32_t*)(g_x + go) = ((uint32_t)__half_as_ushort(h1) << 16) | __half_as_ushort(h0);
    }
    if (tc == 0)
        for (int i = tid; i < 8 * 32; i += 256) {
            int r = i >> 5, cp = (i & 31) * 2;
            *(uint32_t*)(g_x + ((size_t)b * 4104 + r) * CHN + cc * 64 + cp) = 0;
        }
}

// ---------------------------------------------------------------------------
// PHASE 1: C[64 t][128 n(f|g)], K=512. A persistent (72 rows x 256 ch, taps via
// +8 row offset). B-only 3-stage ring. In-register f/g pairing, direct z stores.
// ---------------------------------------------------------------------------
__global__ void __launch_bounds__(256, 3) gemm_p1(
    const float* __restrict__ b0v, const float* __restrict__ b1v)
{
    extern __shared__ unsigned char smraw[];
    const uint32_t sb = smem_u32(smraw);
    const int tid = threadIdx.x, lane = tid & 31, wid = tid >> 5;
    const int wm = wid & 1, wn = wid >> 1;
    const int tt = blockIdx.x, nb = blockIdx.y, b = blockIdx.z;
    const int t0 = tt * 64;

    const __half* Ap = g_x + (size_t)b * 4104 * CHN;
    const __half* Bw = g_w1 + nb * 128 * 512;

    float acc[2][4][4];
    #pragma unroll
    for (int mi = 0; mi < 2; mi++)
        #pragma unroll
        for (int ni = 0; ni < 4; ni++)
            #pragma unroll
            for (int j = 0; j < 4; j++) acc[mi][ni][j] = 0.0f;

    // ---- persistent A load: 72 rows x 32 chunks ----
    for (int i = tid; i < 72 * 32; i += 256) {
        int r = i >> 5, seg = i & 31;
        cp16(sb + r * APITCH + seg * 16, Ap + (size_t)(t0 + r) * CHN + seg * 8);
    }
    asm volatile("cp.async.commit_group;" ::: "memory");

    auto load_stage = [&](int kc, int stg) {
        uint32_t sbase = sb + P1_ABUF + stg * BSTG;
        #pragma unroll
        for (int i = 0; i < 2; i++) {
            int idx = tid + i * 256;
            int r = idx >> 2, seg = idx & 3;
            cp16(sbase + r * 80 + seg * 16, Bw + (size_t)r * 512 + kc * 32 + seg * 8);
        }
        asm volatile("cp.async.commit_group;" ::: "memory");
    };

    load_stage(0, 0);
    load_stage(1, 1);

    int stg = 0;
    for (int kc = 0; kc < 16; kc++) {
        if (kc < 15) asm volatile("cp.async.wait_group 1;" ::: "memory");
        else         asm volatile("cp.async.wait_group 0;" ::: "memory");
        __syncthreads();
        if (kc + 2 < 16) {
            int nstg = stg + 2; if (nstg >= 3) nstg -= 3;
            load_stage(kc + 2, nstg);
        }

        const int koff = (kc < 8) ? 8 : 0;       // tap: x[t] (+8) vs x[t-8]
        const int acolb = (kc & 7) * 64;
        const uint32_t bbase = sb + P1_ABUF + stg * BSTG;
        #pragma unroll
        for (int ks = 0; ks < 2; ks++) {
            uint32_t ah[2][4], bf2[4][2];
            const int arow = lane & 15, acoll = ks * 16 + (lane >> 4) * 8;
            const int brow = (lane & 7) + ((lane >> 4) << 3);
            const int bcol = ks * 16 + ((lane >> 3) & 1) * 8;
            #pragma unroll
            for (int ni2 = 0; ni2 < 2; ni2++) {
                int nbase = ni2 * 64 + wn * 16;   // f rows / g rows
                uint32_t t4[4];
                ldmx4(t4, bbase + (nbase + brow) * 80 + bcol * 2);
                bf2[ni2*2][0] = t4[0]; bf2[ni2*2][1] = t4[1];
                bf2[ni2*2+1][0] = t4[2]; bf2[ni2*2+1][1] = t4[3];
            }
            #pragma unroll
            for (int mi = 0; mi < 2; mi++)
                ldmx4(ah[mi], sb + (koff + wm * 32 + mi * 16 + arow) * APITCH
                               + acolb + acoll * 2);
            #pragma unroll
            for (int mi = 0; mi < 2; mi++)
                #pragma unroll
                for (int ni = 0; ni < 4; ni++)
                    mma_h(acc[mi][ni], ah[mi], bf2[ni]);
        }
        stg++; if (stg >= 3) stg = 0;
    }

    // ---- in-register f/g pairing epilogue ----
    const int r0 = t0 + wm * 32 + (lane >> 2);
    float bfv[2][2], bgv[2][2];
    #pragma unroll
    for (int ni = 0; ni < 2; ni++) {
        int c = nb * 64 + wn * 16 + ni * 8 + (lane & 3) * 2;
        bfv[ni][0] = __ldg(b0v + c); bfv[ni][1] = __ldg(b0v + c + 1);
        bgv[ni][0] = __ldg(b1v + c); bgv[ni][1] = __ldg(b1v + c + 1);
    }
    #pragma unroll
    for (int mi = 0; mi < 2; mi++)
        #pragma unroll
        for (int ni = 0; ni < 2; ni++) {
            int c = nb * 64 + wn * 16 + ni * 8 + (lane & 3) * 2;
            #pragma unroll
            for (int h = 0; h < 2; h++) {
                float f0 = acc[mi][ni][h*2]       + bfv[ni][0];
                float f1 = acc[mi][ni][h*2 + 1]   + bfv[ni][1];
                float g0 = acc[mi][ni+2][h*2]     + bgv[ni][0];
                float g1 = acc[mi][ni+2][h*2 + 1] + bgv[ni][1];
                __half h0 = __float2half_rn(gatedact(f0, g0));
                __half h1 = __float2half_rn(gatedact(f1, g1));
                size_t go = ((size_t)(b * TDIM + r0 + mi * 16 + h * 8)) * CHN + c;
                *(uint32_t*)(g_z + go) =
                    ((uint32_t)__half_as_ushort(h1) << 16) | __half_as_ushort(h0);
            }
        }
}

// ---------------------------------------------------------------------------
// PHASE 2: C[64 t][128 n(res|skip)] = z * W2^T, K=256. A (z) persistent,
// B-only 4-stage ring, smem C transpose staging; x loads hoisted above staging;
// streaming (__stcs) out stores to protect L2 residency of z/weights.
// ---------------------------------------------------------------------------
__global__ void __launch_bounds__(256, 3) gemm_p2(
    const float* __restrict__ x, const float* __restrict__ b0v,
    const float* __restrict__ b1v, float* __restrict__ out)
{
    extern __shared__ unsigned char smraw[];
    const uint32_t sb = smem_u32(smraw);
    const int tid = threadIdx.x, lane = tid & 31, wid = tid >> 5;
    const int wm = wid & 1, wn = wid >> 1;
    const int tt = blockIdx.x, nb = blockIdx.y, b = blockIdx.z;
    const int t0 = tt * 64;

    const __half* Ap = g_z + (size_t)b * TDIM * CHN;
    const __half* Bw = g_w2 + nb * 128 * 256;

    float acc[2][4][4];
    #pragma unroll
    for (int mi = 0; mi < 2; mi++)
        #pragma unroll
        for (int ni = 0; ni < 4; ni++)
            #pragma unroll
            for (int j = 0; j < 4; j++) acc[mi][ni][j] = 0.0f;

    // ---- persistent A (z) load: 64 rows x 32 chunks ----
    for (int i = tid; i < 64 * 32; i += 256) {
        int r = i >> 5, seg = i & 31;
        cp16(sb + r * APITCH + seg * 16, Ap + (size_t)(t0 + r) * CHN + seg * 8);
    }
    asm volatile("cp.async.commit_group;" ::: "memory");

    auto load_stage = [&](int kc, int stg) {
        uint32_t sbase = sb + P2_ABUF + stg * BSTG;
        #pragma unroll
        for (int i = 0; i < 2; i++) {
            int idx = tid + i * 256;
            int r = idx >> 2, seg = idx & 3;
            cp16(sbase + r * 80 + seg * 16, Bw + (size_t)r * 256 + kc * 32 + seg * 8);
        }
        asm volatile("cp.async.commit_group;" ::: "memory");
    };

    load_stage(0, 0);
    load_stage(1, 1);
    load_stage(2, 2);

    int stg = 0;
    for (int kc = 0; kc < 8; kc++) {
        int rem = 7 - kc;
        if (rem >= 2)      asm volatile("cp.async.wait_group 2;" ::: "memory");
        else if (rem == 1) asm volatile("cp.async.wait_group 1;" ::: "memory");
        else               asm volatile("cp.async.wait_group 0;" ::: "memory");
        __syncthreads();
        if (kc + 3 < 8) {
            int nstg = stg + 3; if (nstg >= 4) nstg -= 4;
            load_stage(kc + 3, nstg);
        }

        const uint32_t bbase = sb + P2_ABUF + stg * BSTG;
        #pragma unroll
        for (int ks = 0; ks < 2; ks++) {
            uint32_t ah[2][4], bf2[4][2];
            const int arow = lane & 15, acoll = ks * 16 + (lane >> 4) * 8;
            const int brow = (lane & 7) + ((lane >> 4) << 3);
            const int bcol = ks * 16 + ((lane >> 3) & 1) * 8;
            #pragma unroll
            for (int ni2 = 0; ni2 < 2; ni2++) {
                int nbase = wn * 32 + ni2 * 16;
                uint32_t t4[4];
                ldmx4(t4, bbase + (nbase + brow) * 80 + bcol * 2);
                bf2[ni2*2][0] = t4[0]; bf2[ni2*2][1] = t4[1];
                bf2[ni2*2+1][0] = t4[2]; bf2[ni2*2+1][1] = t4[3];
            }
            #pragma unroll
            for (int mi = 0; mi < 2; mi++)
                ldmx4(ah[mi], sb + (wm * 32 + mi * 16 + arow) * APITCH
                               + kc * 64 + acoll * 2);
            #pragma unroll
            for (int mi = 0; mi < 2; mi++)
                #pragma unroll
                for (int ni = 0; ni < 4; ni++)
                    mma_h(acc[mi][ni], ah[mi], bf2[ni]);
        }
        stg++; if (stg >= 4) stg = 0;
    }
    __syncthreads();

    // ---- hoist residual-x loads above C staging (latency hides under STS) ----
    // iteration k of the output loop: i = tid + k*256, c1 = tid>>4 + 16k; k<4 -> res
    float4 xv4[4];
    size_t goarr[8];
    #pragma unroll
    for (int k = 0; k < 8; k++) {
        int i = tid + k * 256;
        int c1 = i >> 4, mp = (i & 15) * 4;
        goarr[k] = ((size_t)(b * CHN + nb * 64 + ((c1 < 64) ? c1 : c1 - 64))) * TDIM + t0 + mp;
        if (k < 4) xv4[k] = *(const float4*)(x + goarr[k]);
    }

    // ---- stage C through smem [128 n][68 m] (reuses A region) ----
    float* Cs = (float*)smraw;
    {
        const int tr = lane >> 2, tc4 = (lane & 3) * 2;
        #pragma unroll
        for (int mi = 0; mi < 2; mi++)
            #pragma unroll
            for (int ni = 0; ni < 4; ni++) {
                int n0 = wn * 32 + ni * 8 + tc4;
                int m0 = wm * 32 + mi * 16 + tr;
                Cs[n0 * 68 + m0]           = acc[mi][ni][0];
                Cs[(n0 + 1) * 68 + m0]     = acc[mi][ni][1];
                Cs[n0 * 68 + m0 + 8]       = acc[mi][ni][2];
                Cs[(n0 + 1) * 68 + m0 + 8] = acc[mi][ni][3];
            }
    }
    __syncthreads();

    #pragma unroll
    for (int k = 0; k < 8; k++) {
        int i = tid + k * 256;
        int c1 = i >> 4, mp = (i & 15) * 4;
        if (k < 4) {
            float bias = __ldg(b0v + nb * 64 + c1);
            float4 v = make_float4(Cs[c1*68+mp]   + bias + xv4[k].x,
                                   Cs[c1*68+mp+1] + bias + xv4[k].y,
                                   Cs[c1*68+mp+2] + bias + xv4[k].z,
                                   Cs[c1*68+mp+3] + bias + xv4[k].w);
            __stcs((float4*)(out + goarr[k]), v);
        } else {
            float bias = __ldg(b1v + nb * 64 + (c1 - 64));
            float4 v = make_float4(Cs[c1*68+mp]   + bias,
                                   Cs[c1*68+mp+1] + bias,
                                   Cs[c1*68+mp+2] + bias,
                                   Cs[c1*68+mp+3] + bias);
            __stcs((float4*)(out + SKIPOFF + goarr[k]), v);
        }
    }
}

// ---------------------------------------------------------------------------
extern "C" void kernel_launch(void* const* d_in, const int* in_sizes, int n_in,
                              void* d_out, int out_size)
{
    const float* x   = (const float*)d_in[0];
    const float* wf  = (const float*)d_in[1];
    const float* bf  = (const float*)d_in[2];
    const float* wg  = (const float*)d_in[3];
    const float* bg  = (const float*)d_in[4];
    const float* wr  = (const float*)d_in[5];
    const float* br  = (const float*)d_in[6];
    const float* wsk = (const float*)d_in[7];
    const float* bsk = (const float*)d_in[8];
    float* out = (float*)d_out;

    cudaFuncSetAttribute(gemm_p1, cudaFuncAttributeMaxDynamicSharedMemorySize, P1_SMEM);
    cudaFuncSetAttribute(gemm_p2, cudaFuncAttributeMaxDynamicSharedMemorySize, P2_SMEM);

    pack_all_kernel<<<1536 + 2048, 256>>>(x, wf, wg, wr, wsk);
    dim3 grid(64, 4, BATCH);
    gemm_p1<<<grid, 256, P1_SMEM>>>(bf, bg);
    gemm_p2<<<grid, 256, P2_SMEM>>>(x, br, bsk, out);
}